// round 2
// baseline (speedup 1.0000x reference)
#include <cuda_runtime.h>
#include <math.h>

#define Bb 8
#define Nn 1024
#define Dd 512
#define Hh 2048
#define Ll 3
#define ROWS (Bb*Nn)   // 8192

// ---------------- device scratch (static, allocation-free) ----------------
__device__ float g_x[ROWS * Dd];                    // 16.8 MB
__device__ float g_h[ROWS * Dd];                    // 16.8 MB
__device__ float g_attn[(size_t)Bb * Nn * Nn];      // 33.5 MB
__device__ float g_agg[ROWS * Dd];                  // 16.8 MB
__device__ float g_hidden[(size_t)ROWS * Hh];       // 67 MB
__device__ float g_ff[ROWS * Dd];                   // 16.8 MB
__device__ float g_si[ROWS];
__device__ float g_sj[ROWS];

// ---------------- kernel 1: per-row attention projections si, sj ----------
__global__ void k_scores(const float* __restrict__ x, const float* __restrict__ aw)
{
    int row  = blockIdx.x * 8 + (threadIdx.x >> 5);
    int lane = threadIdx.x & 31;
    const float* xr = x + (size_t)row * Dd;
    float s1 = 0.f, s2 = 0.f;
    #pragma unroll 4
    for (int k = lane; k < Dd; k += 32) {
        float v = xr[k];
        s1 += v * aw[k];
        s2 += v * aw[Dd + k];
    }
    #pragma unroll
    for (int o = 16; o; o >>= 1) {
        s1 += __shfl_xor_sync(0xffffffffu, s1, o);
        s2 += __shfl_xor_sync(0xffffffffu, s2, o);
    }
    if (lane == 0) { g_si[row] = s1; g_sj[row] = s2; }
}

// ---------------- kernel 2: masked LeakyReLU softmax row -------------------
__global__ void k_attn(const int* __restrict__ adj, const float* __restrict__ ab_ptr)
{
    const int row = blockIdx.x;            // b*N + i
    const int b = row >> 10;               // /1024
    const int i = row & 1023;
    const float ab = ab_ptr[0];
    const int* arow = adj + (size_t)row * Nn;
    const float* sjb = g_sj + b * Nn;
    const float si = g_si[row];

    float sc[Nn / 256];
    float lmax = -3.4e38f;
    #pragma unroll
    for (int t = 0; t < Nn / 256; t++) {
        int j = threadIdx.x + t * 256;
        float s = si + sjb[j] + ab;
        s = (s >= 0.f) ? s : 0.2f * s;                 // LeakyReLU(0.2)
        bool ok = (arow[j] != 0) | (j == i);
        s = ok ? s : -3.4e38f;
        sc[t] = s;
        lmax = fmaxf(lmax, s);
    }
    __shared__ float red[256];
    red[threadIdx.x] = lmax; __syncthreads();
    #pragma unroll
    for (int s = 128; s; s >>= 1) {
        if (threadIdx.x < s) red[threadIdx.x] = fmaxf(red[threadIdx.x], red[threadIdx.x + s]);
        __syncthreads();
    }
    const float m = red[0];
    __syncthreads();

    float lsum = 0.f;
    #pragma unroll
    for (int t = 0; t < Nn / 256; t++) {
        float e = (sc[t] <= -3.0e38f) ? 0.f : expf(sc[t] - m);
        sc[t] = e;
        lsum += e;
    }
    red[threadIdx.x] = lsum; __syncthreads();
    #pragma unroll
    for (int s = 128; s; s >>= 1) {
        if (threadIdx.x < s) red[threadIdx.x] += red[threadIdx.x + s];
        __syncthreads();
    }
    const float inv = 1.f / red[0];
    float* outr = g_attn + (size_t)row * Nn;
    #pragma unroll
    for (int t = 0; t < Nn / 256; t++)
        outr[threadIdx.x + t * 256] = sc[t] * inv;
}

// ---------------- generic tiled fp32 GEMM (row-major), batched -------------
// C[M,N] = A[M,K] @ B[K,N]  (+bias, +gelu per EPI)
// EPI: 0 = none, 1 = bias + exact gelu, 2 = bias only
template <int EPI>
__global__ void __launch_bounds__(256, 2)
k_gemm(const float* __restrict__ A, const float* __restrict__ Bm,
       float* __restrict__ C, const float* __restrict__ bias,
       int M, int Ncols, int K,
       long long sA, long long sB, long long sC)
{
    constexpr int BM = 128, BN = 128, BK = 8, TM = 8, TN = 8;
    A  += (size_t)blockIdx.z * sA;
    Bm += (size_t)blockIdx.z * sB;
    C  += (size_t)blockIdx.z * sC;

    __shared__ float As[BK * BM];
    __shared__ float Bs[BK * BN];

    const int tid = threadIdx.x;
    const int cRow = blockIdx.y, cCol = blockIdx.x;

    const int innerRowA = tid >> 1,  innerColA = tid & 1;    // 128x8 tile via float4
    const int innerRowB = tid >> 5,  innerColB = tid & 31;   // 8x128 tile via float4
    const int threadRow = tid >> 4,  threadCol = tid & 15;

    A  += (size_t)cRow * BM * K;
    Bm += (size_t)cCol * BN;
    C  += (size_t)cRow * BM * Ncols + (size_t)cCol * BN;

    float acc[TM][TN] = {};
    float regM[TM], regN[TN];

    for (int k0 = 0; k0 < K; k0 += BK) {
        float4 a4 = *(const float4*)(A + (size_t)innerRowA * K + innerColA * 4);
        As[(innerColA * 4 + 0) * BM + innerRowA] = a4.x;
        As[(innerColA * 4 + 1) * BM + innerRowA] = a4.y;
        As[(innerColA * 4 + 2) * BM + innerRowA] = a4.z;
        As[(innerColA * 4 + 3) * BM + innerRowA] = a4.w;
        *(float4*)(Bs + innerRowB * BN + innerColB * 4) =
            *(const float4*)(Bm + (size_t)innerRowB * Ncols + innerColB * 4);
        __syncthreads();

        A  += BK;
        Bm += (size_t)BK * Ncols;

        #pragma unroll
        for (int k = 0; k < BK; k++) {
            #pragma unroll
            for (int i = 0; i < TM; i++) regM[i] = As[k * BM + threadRow * TM + i];
            #pragma unroll
            for (int j = 0; j < TN; j++) regN[j] = Bs[k * BN + threadCol * TN + j];
            #pragma unroll
            for (int i = 0; i < TM; i++)
                #pragma unroll
                for (int j = 0; j < TN; j++)
                    acc[i][j] += regM[i] * regN[j];
        }
        __syncthreads();
    }

    const int colBase = cCol * BN + threadCol * TN;
    #pragma unroll
    for (int i = 0; i < TM; i++) {
        float* crow = C + (size_t)(threadRow * TM + i) * Ncols + threadCol * TN;
        #pragma unroll
        for (int j = 0; j < TN; j += 4) {
            float4 v;
            float e[4];
            #pragma unroll
            for (int q = 0; q < 4; q++) {
                float t = acc[i][j + q];
                if (EPI >= 1) t += bias[colBase + j + q];
                if (EPI == 1) t = 0.5f * t * (1.f + erff(t * 0.70710678118654752f));
                e[q] = t;
            }
            v.x = e[0]; v.y = e[1]; v.z = e[2]; v.w = e[3];
            *(float4*)(crow + j) = v;
        }
    }
}

// ---------------- residual + LayerNorm, one block per row ------------------
__global__ void k_add_ln(const float* __restrict__ a, const float* __restrict__ bvec,
                         const float* __restrict__ g, const float* __restrict__ beta,
                         float* __restrict__ out)
{
    const int row = blockIdx.x;
    const float* ar = a + (size_t)row * Dd;
    const float* br = bvec + (size_t)row * Dd;
    __shared__ float v[Dd];
    __shared__ float red[256];

    float local = 0.f;
    #pragma unroll
    for (int k = threadIdx.x; k < Dd; k += 256) {
        float t = ar[k] + br[k];
        v[k] = t;
        local += t;
    }
    red[threadIdx.x] = local; __syncthreads();
    #pragma unroll
    for (int s = 128; s; s >>= 1) {
        if (threadIdx.x < s) red[threadIdx.x] += red[threadIdx.x + s];
        __syncthreads();
    }
    const float mu = red[0] * (1.f / Dd);
    __syncthreads();

    local = 0.f;
    #pragma unroll
    for (int k = threadIdx.x; k < Dd; k += 256) {
        float d = v[k] - mu;
        local += d * d;
    }
    red[threadIdx.x] = local; __syncthreads();
    #pragma unroll
    for (int s = 128; s; s >>= 1) {
        if (threadIdx.x < s) red[threadIdx.x] += red[threadIdx.x + s];
        __syncthreads();
    }
    const float rstd = rsqrtf(red[0] * (1.f / Dd) + 1e-5f);

    float* orow = out + (size_t)row * Dd;
    #pragma unroll
    for (int k = threadIdx.x; k < Dd; k += 256)
        orow[k] = (v[k] - mu) * rstd * g[k] + beta[k];
}

// ---------------- host launcher --------------------------------------------
extern "C" void kernel_launch(void* const* d_in, const int* in_sizes, int n_in,
                              void* d_out, int out_size)
{
    const float* nf     = (const float*)d_in[0];
    const int*   adj    = (const int*)  d_in[1];
    const float* attn_w = (const float*)d_in[2];
    const float* attn_b = (const float*)d_in[3];
    const float* W1     = (const float*)d_in[4];
    const float* b1     = (const float*)d_in[5];
    const float* W2     = (const float*)d_in[6];
    const float* b2     = (const float*)d_in[7];
    const float* g1     = (const float*)d_in[8];
    const float* beta1  = (const float*)d_in[9];
    const float* g2     = (const float*)d_in[10];
    const float* beta2  = (const float*)d_in[11];
    float* out = (float*)d_out;

    float *xg, *hg, *attng, *aggg, *hidg, *ffg;
    cudaGetSymbolAddress((void**)&xg,    g_x);
    cudaGetSymbolAddress((void**)&hg,    g_h);
    cudaGetSymbolAddress((void**)&attng, g_attn);
    cudaGetSymbolAddress((void**)&aggg,  g_agg);
    cudaGetSymbolAddress((void**)&hidg,  g_hidden);
    cudaGetSymbolAddress((void**)&ffg,   g_ff);

    for (int l = 0; l < Ll; l++) {
        const float* xin  = (l == 0)      ? nf  : xg;
        float*       xout = (l == Ll - 1) ? out : xg;

        // 1) si, sj projections
        k_scores<<<ROWS / 8, 256>>>(xin, attn_w + (size_t)l * 2 * Dd);

        // 2) masked leaky-softmax -> g_attn
        k_attn<<<ROWS, 256>>>(adj, attn_b + l);

        // 3) agg = attn @ x   (batched over B)
        {
            dim3 grid(Dd / 128, Nn / 128, Bb);
            k_gemm<0><<<grid, 256>>>(attng, xin, aggg, nullptr,
                                     Nn, Dd, Nn,
                                     (long long)Nn * Nn, (long long)Nn * Dd,
                                     (long long)Nn * Dd);
        }

        // 4) h = LN(x + agg)
        k_add_ln<<<ROWS, 256>>>(xin, aggg, g1 + (size_t)l * Dd, beta1 + (size_t)l * Dd, hg);

        // 5) hidden = gelu(h @ W1 + b1)
        {
            dim3 grid(Hh / 128, ROWS / 128, 1);
            k_gemm<1><<<grid, 256>>>(hg, W1 + (size_t)l * Dd * Hh, hidg,
                                     b1 + (size_t)l * Hh,
                                     ROWS, Hh, Dd, 0, 0, 0);
        }

        // 6) ff = hidden @ W2 + b2
        {
            dim3 grid(Dd / 128, ROWS / 128, 1);
            k_gemm<2><<<grid, 256>>>(hidg, W2 + (size_t)l * Hh * Dd, ffg,
                                     b2 + (size_t)l * Dd,
                                     ROWS, Dd, Hh, 0, 0, 0);
        }

        // 7) x = LN(h + ff)
        k_add_ln<<<ROWS, 256>>>(hg, ffg, g2 + (size_t)l * Dd, beta2 + (size_t)l * Dd, xout);
    }
}